// round 12
// baseline (speedup 1.0000x reference)
#include <cuda_runtime.h>
#include <math.h>

#define HWX 262144   // 512*512
#define NCH 64
#define KS  576
#define RMAGIC 12582912.0f   // 1.5*2^23 round-to-nearest-even shifter

typedef unsigned long long ull;

// Scratch (__device__ globals; no allocation allowed)
__device__ float g_part[NCH * 16 * 9];  // per (channel, 32-row group) window maxima
__device__ float g_wm[KS];              // per-column weight abs-max
__device__ float g_rk2[NCH * 20];       // duplicated pairs (k0,k0,...,k8,k8,pad,pad)
__device__ float g_sqx;

// ---- packed f32x2 helpers -------------------------------------------------
__device__ __forceinline__ ull pk2(float lo, float hi) {
    ull r; asm("mov.b64 %0, {%1, %2};" : "=l"(r) : "f"(lo), "f"(hi)); return r;
}
__device__ __forceinline__ void upk2(ull v, float& lo, float& hi) {
    asm("mov.b64 {%0, %1}, %2;" : "=f"(lo), "=f"(hi) : "l"(v));
}
__device__ __forceinline__ ull f2fma(ull a, ull b, ull c) {
    ull d; asm("fma.rn.f32x2 %0, %1, %2, %3;" : "=l"(d) : "l"(a), "l"(b), "l"(c)); return d;
}
__device__ __forceinline__ ull f2add(ull a, ull b) {
    ull d; asm("add.rn.f32x2 %0, %1, %2;" : "=l"(d) : "l"(a), "l"(b)); return d;
}
__device__ __forceinline__ ull f2mul(ull a, ull b) {
    ull d; asm("mul.rn.f32x2 %0, %1, %2;" : "=l"(d) : "l"(a), "l"(b)); return d;
}

// ---- L2-policy memory ops -------------------------------------------------
__device__ __forceinline__ void ldg_v8_el(const float* p, float v[8]) {
    unsigned r0, r1, r2, r3, r4, r5, r6, r7;
    asm("ld.global.nc.L2::evict_last.v8.b32 {%0,%1,%2,%3,%4,%5,%6,%7}, [%8];"
        : "=r"(r0), "=r"(r1), "=r"(r2), "=r"(r3),
          "=r"(r4), "=r"(r5), "=r"(r6), "=r"(r7) : "l"(p));
    v[0] = __uint_as_float(r0); v[1] = __uint_as_float(r1);
    v[2] = __uint_as_float(r2); v[3] = __uint_as_float(r3);
    v[4] = __uint_as_float(r4); v[5] = __uint_as_float(r5);
    v[6] = __uint_as_float(r6); v[7] = __uint_as_float(r7);
}
__device__ __forceinline__ void stg_v8_ef(float* p, float4 a, float4 b) {
    asm("st.global.L2::evict_first.v8.b32 [%0], {%1,%2,%3,%4,%5,%6,%7,%8};"
        :: "l"(p),
           "r"(__float_as_uint(a.x)), "r"(__float_as_uint(a.y)),
           "r"(__float_as_uint(a.z)), "r"(__float_as_uint(a.w)),
           "r"(__float_as_uint(b.x)), "r"(__float_as_uint(b.y)),
           "r"(__float_as_uint(b.z)), "r"(__float_as_uint(b.w)) : "memory");
}
__device__ __forceinline__ ull pol_evict_last() {
    ull p; asm("createpolicy.fractional.L2::evict_last.b64 %0, 1.0;" : "=l"(p));
    return p;
}
__device__ __forceinline__ float4 ldg_el(const float4* p, ull pol) {
    float4 v;
    asm("ld.global.nc.L2::cache_hint.v4.f32 {%0,%1,%2,%3}, [%4], %5;"
        : "=f"(v.x), "=f"(v.y), "=f"(v.z), "=f"(v.w) : "l"(p), "l"(pol));
    return v;
}

// ---------------------------------------------------------------------------
// Kernel 1: grid (17, 64). blockIdx.x<16: per-channel windowed abs-max over a
// 32-row group, 8 x LDG.256 per thread. blockIdx.x==16: weight abs-max.
// ---------------------------------------------------------------------------
template <int MODE>  // 0 interior, 1 contains row 0, 2 contains row 511
__device__ __forceinline__ void actmax_loop(const float* p, int t,
                                            bool isC0, bool isC511,
                                            float& mm, float& sm,
                                            float& mc0, float& sc0,
                                            float& mc511, float& sc511) {
#pragma unroll
    for (int k = 0; k < 8; k++) {
        float v[8];
        ldg_v8_el(p + (size_t)(t + 256 * k) * 8, v);
        bool sp = (MODE == 1) ? (k == 0 && t < 64)
                : (MODE == 2) ? (k == 7 && t >= 192) : false;
        float m3;
        if (isC0) {
            m3 = fmaxf(fmaxf(fmaxf(fabsf(v[1]), fabsf(v[2])), fmaxf(fabsf(v[3]), fabsf(v[4]))),
                       fmaxf(fmaxf(fabsf(v[5]), fabsf(v[6])), fabsf(v[7])));
            float a = fabsf(v[0]);
            if (sp) sc0 = fmaxf(sc0, a); else mc0 = fmaxf(mc0, a);
        } else if (isC511) {
            m3 = fmaxf(fmaxf(fmaxf(fabsf(v[0]), fabsf(v[1])), fmaxf(fabsf(v[2]), fabsf(v[3]))),
                       fmaxf(fmaxf(fabsf(v[4]), fabsf(v[5])), fabsf(v[6])));
            float a = fabsf(v[7]);
            if (sp) sc511 = fmaxf(sc511, a); else mc511 = fmaxf(mc511, a);
        } else {
            m3 = fmaxf(fmaxf(fmaxf(fabsf(v[0]), fabsf(v[1])), fmaxf(fabsf(v[2]), fabsf(v[3]))),
                       fmaxf(fmaxf(fabsf(v[4]), fabsf(v[5])), fmaxf(fabsf(v[6]), fabsf(v[7]))));
        }
        if (MODE != 0 && sp) sm = fmaxf(sm, m3); else mm = fmaxf(mm, m3);
    }
}

__global__ __launch_bounds__(256) void actmax_kernel(const float* __restrict__ in,
                                                     const float* __restrict__ w) {
    int ch = blockIdx.y;
    int t  = threadIdx.x;

    __shared__ float swm[8], sws[8];
    __shared__ float e_mc0[4], e_sc0[4], e_mc511[4], e_sc511[4];
    __shared__ float wred[2][9];

    if (blockIdx.x == 16) {
        float wv[9];
        if (t < 64) {
#pragma unroll
            for (int j = 0; j < 9; j++) wv[j] = fabsf(w[t * KS + ch * 9 + j]);
#pragma unroll
            for (int off = 16; off; off >>= 1)
#pragma unroll
                for (int j = 0; j < 9; j++)
                    wv[j] = fmaxf(wv[j], __shfl_xor_sync(0xffffffffu, wv[j], off));
            if ((t & 31) == 0)
#pragma unroll
                for (int j = 0; j < 9; j++) wred[t >> 5][j] = wv[j];
        }
        __syncthreads();
        if (t < 9) g_wm[ch * 9 + t] = fmaxf(wred[0][t], wred[1][t]);
        return;
    }

    int rg = blockIdx.x;  // 0..15, 32 rows each
    const float* p = in + (size_t)ch * HWX + (size_t)rg * 16384;
    int lanepos = t & 63;
    bool isC0 = (lanepos == 0), isC511 = (lanepos == 63);

    float mm = 0.f, sm = 0.f, mc0 = 0.f, sc0 = 0.f, mc511 = 0.f, sc511 = 0.f;
    if (rg == 0)       actmax_loop<1>(p, t, isC0, isC511, mm, sm, mc0, sc0, mc511, sc511);
    else if (rg == 15) actmax_loop<2>(p, t, isC0, isC511, mm, sm, mc0, sc0, mc511, sc511);
    else               actmax_loop<0>(p, t, isC0, isC511, mm, sm, mc0, sc0, mc511, sc511);

#pragma unroll
    for (int off = 16; off; off >>= 1) {
        mm = fmaxf(mm, __shfl_xor_sync(0xffffffffu, mm, off));
        sm = fmaxf(sm, __shfl_xor_sync(0xffffffffu, sm, off));
    }
    if ((t & 31) == 0) { swm[t >> 5] = mm; sws[t >> 5] = sm; }
    if (isC0)   { e_mc0[t >> 6] = mc0;     e_sc0[t >> 6] = sc0; }
    if (isC511) { e_mc511[t >> 6] = mc511; e_sc511[t >> 6] = sc511; }
    __syncthreads();

    if (t == 0) {
        float Rm = 0.f, Sm = 0.f;
#pragma unroll
        for (int i = 0; i < 8; i++) { Rm = fmaxf(Rm, swm[i]); Sm = fmaxf(Sm, sws[i]); }
        float Rc0 = 0.f, Sc0 = 0.f, Rc511 = 0.f, Sc511 = 0.f;
#pragma unroll
        for (int i = 0; i < 4; i++) {
            Rc0   = fmaxf(Rc0, e_mc0[i]);     Sc0   = fmaxf(Sc0, e_sc0[i]);
            Rc511 = fmaxf(Rc511, e_mc511[i]); Sc511 = fmaxf(Sc511, e_sc511[i]);
        }
        float r9[3] = { fmaxf(Rc0, Rm), fmaxf(fmaxf(Rc0, Rc511), Rm), fmaxf(Rm, Rc511) };
        float s9[3] = { fmaxf(Sc0, Sm), fmaxf(fmaxf(Sc0, Sc511), Sm), fmaxf(Sm, Sc511) };
        int excl = (rg == 0) ? 2 : (rg == 15) ? 0 : -1;
        float* dst = &g_part[((size_t)ch * 16 + rg) * 9];
#pragma unroll
        for (int kh = 0; kh < 3; kh++)
#pragma unroll
            for (int kw = 0; kw < 3; kw++)
                dst[kh * 3 + kw] = (kh == excl) ? r9[kw] : fmaxf(r9[kw], s9[kw]);
    }
}

// ---------------------------------------------------------------------------
// Kernel 2: merged scale + wq (64 blocks, redundant tiny reduction).
// ---------------------------------------------------------------------------
__global__ __launch_bounds__(576) void scale_wq_kernel(const float* __restrict__ w,
                                                       float* __restrict__ out) {
    __shared__ float red_ax[18], red_wx[18];
    __shared__ float s_q[2];

    int k = threadIdx.x;  // c*9 + t
    int c = k / 9, t = k % 9;

    float act = 0.f;
#pragma unroll
    for (int b = 0; b < 16; b++)
        act = fmaxf(act, g_part[((size_t)c * 16 + b) * 9 + t]);
    float wm = g_wm[k];

    float sc = sqrtf(act) / sqrtf(wm);
    if (sc == 0.f) sc = 1.f;

    float ax = act / sc;
    float wx = wm * sc;
#pragma unroll
    for (int off = 16; off; off >>= 1) {
        ax = fmaxf(ax, __shfl_xor_sync(0xffffffffu, ax, off));
        wx = fmaxf(wx, __shfl_xor_sync(0xffffffffu, wx, off));
    }
    if ((k & 31) == 0) { red_ax[k >> 5] = ax; red_wx[k >> 5] = wx; }
    __syncthreads();
    if (k == 0) {
        float a = 0.f, b = 0.f;
        for (int i = 0; i < 18; i++) { a = fmaxf(a, red_ax[i]); b = fmaxf(b, red_wx[i]); }
        s_q[0] = (a > 0.f) ? a / 127.f : 1.f;   // s_qx
        s_q[1] = (b > 0.f) ? b / 127.f : 1.f;   // s_qw
    }
    __syncthreads();
    float sqx = s_q[0], sqw = s_q[1];
    float rqw = 1.0f / sqw;

    if (blockIdx.x == 0) {
        if (k == 0) g_sqx = sqx;
        float rk = 1.0f / (sc * sqx);
        g_rk2[c * 20 + 2 * t]     = rk;
        g_rk2[c * 20 + 2 * t + 1] = rk;
    }

    int co = blockIdx.x;
    int kh = t / 3, kw = t % 3;
    float u = (w[co * KS + k] * sc) * rqw;
    u = fminf(fmaxf(u, -127.f), 127.f);
    out[co * KS + kh * 192 + kw * 64 + c] = rintf(u) * sqw;
}

// ---------------------------------------------------------------------------
// Kernel 3: fused 9-tap quantize-fold + NCHW->NHWC transpose.
// 4 h-rows per block (grid 8x128 -> ~1.4 waves): amortizes the srk2 prologue
// and wave transitions. Output via STG.256 evict_first.
// ---------------------------------------------------------------------------
__global__ __launch_bounds__(256) void main_kernel(const float* __restrict__ in,
                                                   float* __restrict__ out) {
    __shared__ __align__(16) float srk2[NCH * 20];
    __shared__ float tile[64 * 64];

    int tid = threadIdx.x;
    {
        float4* s4 = reinterpret_cast<float4*>(srk2);
        const float4* g4 = reinterpret_cast<const float4*>(g_rk2);
        s4[tid] = g4[tid];
        if (tid < 64) s4[256 + tid] = g4[256 + tid];
    }
    float sq = g_sqx;

    int h0   = blockIdx.y * 4;
    int wblk = blockIdx.x * 64;
    int w4   = tid & 15;
    int cbg  = tid >> 4;
    int cb   = cbg * 4;
    int wloc = w4 * 4;
    ull polL = pol_evict_last();

    float cm0[4], cm2[4];
#pragma unroll
    for (int j = 0; j < 4; j++) {
        int gw = wblk + wloc + j;
        cm0[j] = (gw != 511) ? sq : 0.f;
        cm2[j] = (gw != 0)   ? sq : 0.f;
    }
    ull CW0[2], CW2[2];
    const ull CW1 = pk2(sq, sq);
#pragma unroll
    for (int p = 0; p < 2; p++) {
        CW0[p] = pk2(cm0[2 * p], cm0[2 * p + 1]);
        CW2[p] = pk2(cm2[2 * p], cm2[2 * p + 1]);
    }
    const ull MM2 = pk2(RMAGIC, RMAGIC);
    const ull NM2 = pk2(-RMAGIC, -RMAGIC);
    __syncthreads();

#pragma unroll
    for (int r = 0; r < 4; r++) {
        int h = h0 + r;
        float rf0 = (h != 511) ? 1.f : 0.f;
        float rf2 = (h != 0)   ? 1.f : 0.f;
        ull RH0 = pk2(rf0, rf0), RH2 = pk2(rf2, rf2);

        float a[4][4];
        size_t base = (size_t)h * 512 + wblk + wloc;
#pragma unroll
        for (int i = 0; i < 4; i++) {
            int c = cb + i;
            const double2* kt = reinterpret_cast<const double2*>(&srk2[c * 20]);
            double2 A = kt[0], B = kt[1], C2 = kt[2], D = kt[3];
            double   E = *reinterpret_cast<const double*>(&srk2[c * 20 + 16]);
            ull KK[9] = { __double_as_longlong(A.x), __double_as_longlong(A.y),
                          __double_as_longlong(B.x), __double_as_longlong(B.y),
                          __double_as_longlong(C2.x), __double_as_longlong(C2.y),
                          __double_as_longlong(D.x), __double_as_longlong(D.y),
                          __double_as_longlong(E) };
            float4 v = ldg_el(reinterpret_cast<const float4*>(in + (size_t)c * HWX + base), polL);
            ull X2[2] = { pk2(v.x, v.y), pk2(v.z, v.w) };
#pragma unroll
            for (int p = 0; p < 2; p++) {
                ull X = X2[p];
                ull R[9];
#pragma unroll
                for (int tt = 0; tt < 9; tt++)
                    R[tt] = f2add(f2fma(X, KK[tt], MM2), NM2);
                ull row0 = f2fma(R[2], CW2[p], f2fma(R[0], CW0[p], f2mul(R[1], CW1)));
                ull row1 = f2fma(R[5], CW2[p], f2fma(R[3], CW0[p], f2mul(R[4], CW1)));
                ull row2 = f2fma(R[8], CW2[p], f2fma(R[6], CW0[p], f2mul(R[7], CW1)));
                ull acc  = f2fma(row0, RH0, f2fma(row2, RH2, row1));
                upk2(acc, a[i][2 * p], a[i][2 * p + 1]);
            }
        }

        if (r) __syncthreads();   // previous row's tile reads complete
#pragma unroll
        for (int j = 0; j < 4; j++) {
            int row = wloc + j;
            int col = (cbg ^ w4) << 2;
            *reinterpret_cast<float4*>(&tile[row * 64 + col]) =
                make_float4(a[0][j], a[1][j], a[2][j], a[3][j]);
        }
        __syncthreads();

        // 256-bit coalesced NHWC stores: 8 channels per store
        int cg8 = tid & 7;
        int wr  = tid >> 3;       // 0..31
        float* ob = out + 36864 + ((size_t)h * 512 + wblk) * 64;
#pragma unroll
        for (int jj = 0; jj < 2; jj++) {
            int w  = wr + 32 * jj;
            int sw = w >> 2;
            float4 t0 = *reinterpret_cast<const float4*>(
                &tile[w * 64 + (((2 * cg8) ^ sw) << 2)]);
            float4 t1 = *reinterpret_cast<const float4*>(
                &tile[w * 64 + (((2 * cg8 + 1) ^ sw) << 2)]);
            stg_v8_ef(&ob[(size_t)w * 64 + cg8 * 8], t0, t1);
        }
    }
}

// ---------------------------------------------------------------------------
extern "C" void kernel_launch(void* const* d_in, const int* in_sizes, int n_in,
                              void* d_out, int out_size) {
    const float* in;
    const float* w;
    if (in_sizes[0] == 64 * 512 * 512) { in = (const float*)d_in[0]; w = (const float*)d_in[1]; }
    else                               { in = (const float*)d_in[1]; w = (const float*)d_in[0]; }
    float* out = (float*)d_out;

    dim3 g1(17, 64);
    actmax_kernel<<<g1, 256>>>(in, w);
    scale_wq_kernel<<<64, 576>>>(w, out);
    dim3 g3(8, 128);
    main_kernel<<<g3, 256>>>(in, out);
}